// round 2
// baseline (speedup 1.0000x reference)
#include <cuda_runtime.h>
#include <math.h>

typedef unsigned long long u64;

__device__ __forceinline__ u64 pack2(float lo, float hi){
    u64 d; asm("mov.b64 %0, {%1, %2};" : "=l"(d) : "f"(lo), "f"(hi)); return d;
}
__device__ __forceinline__ u64 fma2(u64 a, u64 b, u64 c){
    u64 d; asm("fma.rn.f32x2 %0, %1, %2, %3;" : "=l"(d) : "l"(a), "l"(b), "l"(c)); return d;
}
__device__ __forceinline__ u64 mul2(u64 a, u64 b){
    u64 d; asm("mul.rn.f32x2 %0, %1, %2;" : "=l"(d) : "l"(a), "l"(b)); return d;
}
__device__ __forceinline__ float lo2(u64 v){ return __int_as_float((unsigned)(v & 0xffffffffull)); }
__device__ __forceinline__ float hi2(u64 v){ return __int_as_float((unsigned)(v >> 32)); }

#define NB_THREADS 224  // 7 warps; threads 0..195 own one 2x2 patch each

__global__ __launch_bounds__(NB_THREADS)
void fraud_fused_kernel(
    const float* __restrict__ x,
    const float* __restrict__ w_in,  const float* __restrict__ b_in,
    const float* __restrict__ scale_in, const float* __restrict__ shift_in,
    const float* __restrict__ Wc,    const float* __restrict__ bc,
    const float* __restrict__ scalec, const float* __restrict__ shiftc,
    const float* __restrict__ w_out, const float* __restrict__ b_out,
    const float* __restrict__ U_re,  const float* __restrict__ U_im,
    const float* __restrict__ w_cls, const float* __restrict__ b_cls,
    float* __restrict__ out, int Lc)
{
    // su[m*16 + k] = packed (U_re[k][m], U_im[k][m])  -- transposed for m-outer matvec
    __shared__ __align__(16) u64 su[256];
    __shared__ float red_s[7], red_p[7], red_q[7];

    const int tid = threadIdx.x;
    const int img = blockIdx.x;

    for (int i = tid; i < 256; i += NB_THREADS) {
        int k = i & 15, m = i >> 4;
        su[i] = pack2(__ldg(U_re + k*16 + m), __ldg(U_im + k*16 + m));
    }
    __syncthreads();

    float s_q = 0.f;   // this patch's weighted quantum-feature contribution to the logit
    float sp  = 0.f;   // partial pixel sum   (for mean)
    float sqs = 0.f;   // partial pixel sumsq (for std)

    if (tid < 196) {
        const int r = tid / 14, c = tid - r * 14;
        const float* px = x + (size_t)img * 784 + (2*r) * 28 + 2*c;
        float2 top = *reinterpret_cast<const float2*>(px);
        float2 bot = *reinterpret_cast<const float2*>(px + 28);
        float x00 = top.x, x01 = top.y, x10 = bot.x, x11 = bot.y;

        sp  = x00 + x01 + x10 + x11;
        sqs = fmaf(x00,x00, fmaf(x01,x01, fmaf(x10,x10, x11*x11)));

        // RY(|0>) amplitudes per qubit: (cos(x/2), sin(x/2))
        float c0,s0,c1,s1,c2,s2,c3,s3;
        __sincosf(0.5f*x00, &s0, &c0);
        __sincosf(0.5f*x01, &s1, &c1);
        __sincosf(0.5f*x10, &s2, &c2);
        __sincosf(0.5f*x11, &s3, &c3);

        // product state psi[m] = a0[b3] a1[b2] a2[b1] a3[b0], wire0 = MSB
        float p01[4]  = { c0*c1, c0*s1, s0*c1, s0*s1 };
        float p012[8];
        #pragma unroll
        for (int t = 0; t < 4; t++){ p012[2*t] = p01[t]*c2; p012[2*t+1] = p01[t]*s2; }
        float psi[16];
        #pragma unroll
        for (int t = 0; t < 8; t++){ psi[2*t] = p012[t]*c3; psi[2*t+1] = p012[t]*s3; }

        // complex matvec (re_k, im_k) packed in f32x2: acc[k] += U2[m][k] * (psi_m, psi_m)
        u64 acc[16];
        #pragma unroll
        for (int k = 0; k < 16; k++) acc[k] = 0ull;

        #pragma unroll
        for (int m = 0; m < 16; m++){
            u64 pm = pack2(psi[m], psi[m]);
            const ulonglong2* row = reinterpret_cast<const ulonglong2*>(su + m*16);
            #pragma unroll
            for (int kk = 0; kk < 8; kk++){
                ulonglong2 uv = row[kk];           // uniform LDS.128 broadcast
                acc[2*kk]   = fma2(uv.x, pm, acc[2*kk]);
                acc[2*kk+1] = fma2(uv.y, pm, acc[2*kk+1]);
            }
        }

        // v_k = sum_j w_cls[1+4p+j] * Z[k][j], Z = +-1 by bit (3-j) of k.
        const float* wq = w_cls + 1 + 4*tid;
        float w0 = __ldg(wq+0), w1 = __ldg(wq+1), w2 = __ldg(wq+2), w3 = __ldg(wq+3);
        float A[4]  = {  w0+w1,  w0-w1, -w0+w1, -w0-w1 };  // bits (b3,b2) -> k>>2
        float Bv[4] = {  w2+w3,  w2-w3, -w2+w3, -w2-w3 };  // bits (b1,b0) -> k&3

        #pragma unroll
        for (int k = 0; k < 16; k++){
            u64 s2_ = mul2(acc[k], acc[k]);        // (re^2, im^2)
            float pr = lo2(s2_) + hi2(s2_);        // probs_k
            s_q = fmaf(A[k>>2] + Bv[k&3], pr, s_q);
        }
    }

    // block reduction: quantum logit contribution + pixel sum/sumsq
    #pragma unroll
    for (int off = 16; off > 0; off >>= 1){
        s_q += __shfl_down_sync(0xffffffffu, s_q, off);
        sp  += __shfl_down_sync(0xffffffffu, sp,  off);
        sqs += __shfl_down_sync(0xffffffffu, sqs, off);
    }
    const int warp = tid >> 5, lane = tid & 31;
    if (lane == 0){ red_s[warp] = s_q; red_p[warp] = sp; red_q[warp] = sqs; }
    __syncthreads();

    if (tid == 0){
        float Q = 0.f, S = 0.f, S2 = 0.f;
        #pragma unroll
        for (int w = 0; w < 7; w++){ Q += red_s[w]; S += red_p[w]; S2 += red_q[w]; }

        // classical branch: mean + unbiased std -> tiny tanh MLP -> scalar
        float mean = S * (1.f/784.f);
        float var  = (S2 - S*S*(1.f/784.f)) * (1.f/783.f);
        float stdv = sqrtf(fmaxf(var, 0.f));
        float h0 = mean, h1 = stdv;

        float t0 = tanhf(fmaf(w_in[0],h0, fmaf(w_in[1],h1, b_in[0]))) * scale_in[0] + shift_in[0];
        float t1 = tanhf(fmaf(w_in[2],h0, fmaf(w_in[3],h1, b_in[1]))) * scale_in[1] + shift_in[1];
        h0 = t0; h1 = t1;
        for (int i = 0; i < Lc; i++){
            float u0 = tanhf(fmaf(Wc[i*4+0],h0, fmaf(Wc[i*4+1],h1, bc[i*2+0]))) * scalec[i*2+0] + shiftc[i*2+0];
            float u1 = tanhf(fmaf(Wc[i*4+2],h0, fmaf(Wc[i*4+3],h1, bc[i*2+1]))) * scalec[i*2+1] + shiftc[i*2+1];
            h0 = u0; h1 = u1;
        }
        float cls   = fmaf(w_out[0],h0, fmaf(w_out[1],h1, b_out[0]));
        float logit = fmaf(w_cls[0], cls, b_cls[0]) + Q;
        out[img] = 1.f / (1.f + expf(-logit));
    }
}

extern "C" void kernel_launch(void* const* d_in, const int* in_sizes, int n_in,
                              void* d_out, int out_size)
{
    const float* x        = (const float*)d_in[0];
    const float* w_in     = (const float*)d_in[1];
    const float* b_in     = (const float*)d_in[2];
    const float* scale_in = (const float*)d_in[3];
    const float* shift_in = (const float*)d_in[4];
    const float* Wc       = (const float*)d_in[5];
    const float* bc       = (const float*)d_in[6];
    const float* scalec   = (const float*)d_in[7];
    const float* shiftc   = (const float*)d_in[8];
    const float* w_out    = (const float*)d_in[9];
    const float* b_out    = (const float*)d_in[10];
    const float* U_re     = (const float*)d_in[11];
    const float* U_im     = (const float*)d_in[12];
    const float* w_cls    = (const float*)d_in[13];
    const float* b_cls    = (const float*)d_in[14];
    float* out = (float*)d_out;

    const int bsz = in_sizes[0] / 784;
    const int Lc  = in_sizes[5] / 4;

    fraud_fused_kernel<<<bsz, NB_THREADS>>>(
        x, w_in, b_in, scale_in, shift_in, Wc, bc, scalec, shiftc,
        w_out, b_out, U_re, U_im, w_cls, b_cls, out, Lc);
}

// round 3
// speedup vs baseline: 1.1091x; 1.1091x over previous
#include <cuda_runtime.h>
#include <math.h>

typedef unsigned long long u64;

__device__ __forceinline__ u64 pack2(float lo, float hi){
    u64 d; asm("mov.b64 %0, {%1, %2};" : "=l"(d) : "f"(lo), "f"(hi)); return d;
}
__device__ __forceinline__ u64 fma2(u64 a, u64 b, u64 c){
    u64 d; asm("fma.rn.f32x2 %0, %1, %2, %3;" : "=l"(d) : "l"(a), "l"(b), "l"(c)); return d;
}
__device__ __forceinline__ u64 mul2(u64 a, u64 b){
    u64 d; asm("mul.rn.f32x2 %0, %1, %2;" : "=l"(d) : "l"(a), "l"(b)); return d;
}
__device__ __forceinline__ float lo2(u64 v){ return __int_as_float((unsigned)(v & 0xffffffffull)); }
__device__ __forceinline__ float hi2(u64 v){ return __int_as_float((unsigned)(v >> 32)); }

#define NB_THREADS 224  // 7 warps; threads 0..195 own one 2x2 patch position for TWO images

__device__ __forceinline__ void build_psi(float x00, float x01, float x10, float x11,
                                          float* __restrict__ psi)
{
    float c0,s0,c1,s1,c2,s2,c3,s3;
    __sincosf(0.5f*x00, &s0, &c0);
    __sincosf(0.5f*x01, &s1, &c1);
    __sincosf(0.5f*x10, &s2, &c2);
    __sincosf(0.5f*x11, &s3, &c3);
    float p01[4]  = { c0*c1, c0*s1, s0*c1, s0*s1 };
    float p012[8];
    #pragma unroll
    for (int t = 0; t < 4; t++){ p012[2*t] = p01[t]*c2; p012[2*t+1] = p01[t]*s2; }
    #pragma unroll
    for (int t = 0; t < 8; t++){ psi[2*t] = p012[t]*c3; psi[2*t+1] = p012[t]*s3; }
}

__device__ __forceinline__ float classical_head(
    float S, float S2,
    const float* __restrict__ w_in,  const float* __restrict__ b_in,
    const float* __restrict__ scale_in, const float* __restrict__ shift_in,
    const float* __restrict__ Wc,    const float* __restrict__ bc,
    const float* __restrict__ scalec, const float* __restrict__ shiftc,
    const float* __restrict__ w_out, const float* __restrict__ b_out, int Lc)
{
    float mean = S * (1.f/784.f);
    float var  = (S2 - S*S*(1.f/784.f)) * (1.f/783.f);
    float stdv = sqrtf(fmaxf(var, 0.f));
    float h0 = mean, h1 = stdv;
    float t0 = tanhf(fmaf(w_in[0],h0, fmaf(w_in[1],h1, b_in[0]))) * scale_in[0] + shift_in[0];
    float t1 = tanhf(fmaf(w_in[2],h0, fmaf(w_in[3],h1, b_in[1]))) * scale_in[1] + shift_in[1];
    h0 = t0; h1 = t1;
    for (int i = 0; i < Lc; i++){
        float u0 = tanhf(fmaf(Wc[i*4+0],h0, fmaf(Wc[i*4+1],h1, bc[i*2+0]))) * scalec[i*2+0] + shiftc[i*2+0];
        float u1 = tanhf(fmaf(Wc[i*4+2],h0, fmaf(Wc[i*4+3],h1, bc[i*2+1]))) * scalec[i*2+1] + shiftc[i*2+1];
        h0 = u0; h1 = u1;
    }
    return fmaf(w_out[0],h0, fmaf(w_out[1],h1, b_out[0]));
}

__global__ __launch_bounds__(NB_THREADS)
void fraud_fused_kernel(
    const float* __restrict__ x,
    const float* __restrict__ w_in,  const float* __restrict__ b_in,
    const float* __restrict__ scale_in, const float* __restrict__ shift_in,
    const float* __restrict__ Wc,    const float* __restrict__ bc,
    const float* __restrict__ scalec, const float* __restrict__ shiftc,
    const float* __restrict__ w_out, const float* __restrict__ b_out,
    const float* __restrict__ U_re,  const float* __restrict__ U_im,
    const float* __restrict__ w_cls, const float* __restrict__ b_cls,
    float* __restrict__ out, int Lc, int bsz)
{
    // su[m*16 + k] = packed (U_re[k][m], U_im[k][m])  -- transposed for m-outer matvec
    __shared__ __align__(16) u64 su[256];
    __shared__ float redA_s[7], redA_p[7], redA_q[7];
    __shared__ float redB_s[7], redB_p[7], redB_q[7];

    const int tid  = threadIdx.x;
    const int imgA = 2 * blockIdx.x;
    const int imgB = imgA + 1;
    const bool doB = (imgB < bsz);

    for (int i = tid; i < 256; i += NB_THREADS) {
        int k = i & 15, m = i >> 4;
        su[i] = pack2(__ldg(U_re + k*16 + m), __ldg(U_im + k*16 + m));
    }
    __syncthreads();

    float sA_q = 0.f, sA_p = 0.f, sA_s = 0.f;
    float sB_q = 0.f, sB_p = 0.f, sB_s = 0.f;

    if (tid < 196) {
        const int r = tid / 14, c = tid - r * 14;
        const size_t off = (size_t)(2*r) * 28 + 2*c;

        const float* pxA = x + (size_t)imgA * 784 + off;
        float2 tA = *reinterpret_cast<const float2*>(pxA);
        float2 bA = *reinterpret_cast<const float2*>(pxA + 28);

        const float* pxB = x + (size_t)(doB ? imgB : imgA) * 784 + off;
        float2 tB = *reinterpret_cast<const float2*>(pxB);
        float2 bB = *reinterpret_cast<const float2*>(pxB + 28);

        sA_p = tA.x + tA.y + bA.x + bA.y;
        sA_s = fmaf(tA.x,tA.x, fmaf(tA.y,tA.y, fmaf(bA.x,bA.x, bA.y*bA.y)));
        sB_p = tB.x + tB.y + bB.x + bB.y;
        sB_s = fmaf(tB.x,tB.x, fmaf(tB.y,tB.y, fmaf(bB.x,bB.x, bB.y*bB.y)));

        float psiA[16], psiB[16];
        build_psi(tA.x, tA.y, bA.x, bA.y, psiA);
        build_psi(tB.x, tB.y, bB.x, bB.y, psiB);

        u64 accA[16], accB[16];
        #pragma unroll
        for (int k = 0; k < 16; k++){ accA[k] = 0ull; accB[k] = 0ull; }

        // complex matvec for both images: each U element loaded ONCE, used twice
        #pragma unroll
        for (int m = 0; m < 16; m++){
            u64 pA = pack2(psiA[m], psiA[m]);
            u64 pB = pack2(psiB[m], psiB[m]);
            const ulonglong2* row = reinterpret_cast<const ulonglong2*>(su + m*16);
            #pragma unroll
            for (int kk = 0; kk < 8; kk++){
                ulonglong2 uv = row[kk];           // uniform LDS.128 broadcast
                accA[2*kk]   = fma2(uv.x, pA, accA[2*kk]);
                accA[2*kk+1] = fma2(uv.y, pA, accA[2*kk+1]);
                accB[2*kk]   = fma2(uv.x, pB, accB[2*kk]);
                accB[2*kk+1] = fma2(uv.y, pB, accB[2*kk+1]);
            }
        }

        // v_k = sum_j w_cls[1+4p+j] * Z[k][j], Z = +-1 by bit (3-j) of k.
        const float* wq = w_cls + 1 + 4*tid;
        float w0 = __ldg(wq+0), w1 = __ldg(wq+1), w2 = __ldg(wq+2), w3 = __ldg(wq+3);
        float Av[4] = {  w0+w1,  w0-w1, -w0+w1, -w0-w1 };
        float Bv[4] = {  w2+w3,  w2-w3, -w2+w3, -w2-w3 };

        #pragma unroll
        for (int k = 0; k < 16; k++){
            float vk = Av[k>>2] + Bv[k&3];
            u64 a2 = mul2(accA[k], accA[k]);
            u64 b2 = mul2(accB[k], accB[k]);
            sA_q = fmaf(vk, lo2(a2) + hi2(a2), sA_q);
            sB_q = fmaf(vk, lo2(b2) + hi2(b2), sB_q);
        }
    }

    #pragma unroll
    for (int off = 16; off > 0; off >>= 1){
        sA_q += __shfl_down_sync(0xffffffffu, sA_q, off);
        sA_p += __shfl_down_sync(0xffffffffu, sA_p, off);
        sA_s += __shfl_down_sync(0xffffffffu, sA_s, off);
        sB_q += __shfl_down_sync(0xffffffffu, sB_q, off);
        sB_p += __shfl_down_sync(0xffffffffu, sB_p, off);
        sB_s += __shfl_down_sync(0xffffffffu, sB_s, off);
    }
    const int warp = tid >> 5, lane = tid & 31;
    if (lane == 0){
        redA_s[warp] = sA_q; redA_p[warp] = sA_p; redA_q[warp] = sA_s;
        redB_s[warp] = sB_q; redB_p[warp] = sB_p; redB_q[warp] = sB_s;
    }
    __syncthreads();

    // two leader threads in different warps finish the two images in parallel
    if (tid == 0){
        float Q = 0.f, S = 0.f, S2 = 0.f;
        #pragma unroll
        for (int w = 0; w < 7; w++){ Q += redA_s[w]; S += redA_p[w]; S2 += redA_q[w]; }
        float cls = classical_head(S, S2, w_in, b_in, scale_in, shift_in,
                                   Wc, bc, scalec, shiftc, w_out, b_out, Lc);
        float logit = fmaf(w_cls[0], cls, b_cls[0]) + Q;
        out[imgA] = 1.f / (1.f + expf(-logit));
    }
    if (tid == 32 && doB){
        float Q = 0.f, S = 0.f, S2 = 0.f;
        #pragma unroll
        for (int w = 0; w < 7; w++){ Q += redB_s[w]; S += redB_p[w]; S2 += redB_q[w]; }
        float cls = classical_head(S, S2, w_in, b_in, scale_in, shift_in,
                                   Wc, bc, scalec, shiftc, w_out, b_out, Lc);
        float logit = fmaf(w_cls[0], cls, b_cls[0]) + Q;
        out[imgB] = 1.f / (1.f + expf(-logit));
    }
}

extern "C" void kernel_launch(void* const* d_in, const int* in_sizes, int n_in,
                              void* d_out, int out_size)
{
    const float* x        = (const float*)d_in[0];
    const float* w_in     = (const float*)d_in[1];
    const float* b_in     = (const float*)d_in[2];
    const float* scale_in = (const float*)d_in[3];
    const float* shift_in = (const float*)d_in[4];
    const float* Wc       = (const float*)d_in[5];
    const float* bc       = (const float*)d_in[6];
    const float* scalec   = (const float*)d_in[7];
    const float* shiftc   = (const float*)d_in[8];
    const float* w_out    = (const float*)d_in[9];
    const float* b_out    = (const float*)d_in[10];
    const float* U_re     = (const float*)d_in[11];
    const float* U_im     = (const float*)d_in[12];
    const float* w_cls    = (const float*)d_in[13];
    const float* b_cls    = (const float*)d_in[14];
    float* out = (float*)d_out;

    const int bsz = in_sizes[0] / 784;
    const int Lc  = in_sizes[5] / 4;
    const int grid = (bsz + 1) / 2;

    fraud_fused_kernel<<<grid, NB_THREADS>>>(
        x, w_in, b_in, scale_in, shift_in, Wc, bc, scalec, shiftc,
        w_out, b_out, U_re, U_im, w_cls, b_cls, out, Lc, bsz);
}

// round 5
// speedup vs baseline: 1.5172x; 1.3680x over previous
#include <cuda_runtime.h>
#include <cstdint>
#include <math.h>

typedef uint32_t u32;
typedef unsigned long long u64;

__device__ __forceinline__ u64 pack2(float lo, float hi){
    u64 d; asm("mov.b64 %0, {%1, %2};" : "=l"(d) : "f"(lo), "f"(hi)); return d;
}
__device__ __forceinline__ u64 fma2(u64 a, u64 b, u64 c){
    u64 d; asm("fma.rn.f32x2 %0, %1, %2, %3;" : "=l"(d) : "l"(a), "l"(b), "l"(c)); return d;
}
__device__ __forceinline__ float lo2(u64 v){ return __int_as_float((unsigned)(v & 0xffffffffull)); }
__device__ __forceinline__ float hi2(u64 v){ return __int_as_float((unsigned)(v >> 32)); }

// ---------------- scratch ----------------
// g_M[p][n*8+m2] = packed (M_p[2*m2][n], M_p[2*m2+1][n]); M_p symmetric 16x16.
__device__ u64   g_M[196 * 128];
// per-(image, patch-row) partials: [img][r][ {s_q, sum, sumsq} ]
__device__ float g_part[16384 * 14 * 3];

// ---------------- kernel 0: build the 196 folded matrices ----------------
// M_p[m][n] = sum_k v_k(p) * (U_re[k][m]*U_re[k][n] + U_im[k][m]*U_im[k][n])
// v_k(p)    = sum_j w_cls[1+4p+j] * Z[k][j],  Z[k][j] = 1-2*((k>>(3-j))&1)
__global__ void build_M_kernel(const float* __restrict__ U_re,
                               const float* __restrict__ U_im,
                               const float* __restrict__ w_cls)
{
    const int p  = blockIdx.x;        // 0..195
    const int t  = threadIdx.x;       // 0..127
    const int n  = t >> 3;            // 0..15
    const int m2 = t & 7;             // 0..7  (rows 2*m2, 2*m2+1)

    const float* wq = w_cls + 1 + 4 * p;
    float w0 = wq[0], w1 = wq[1], w2 = wq[2], w3 = wq[3];

    float M0 = 0.f, M1 = 0.f;
    #pragma unroll
    for (int k = 0; k < 16; k++) {
        float vk = ((k & 8) ? -w0 : w0) + ((k & 4) ? -w1 : w1)
                 + ((k & 2) ? -w2 : w2) + ((k & 1) ? -w3 : w3);
        float urn = U_re[k * 16 + n],      uin = U_im[k * 16 + n];
        float ur0 = U_re[k * 16 + 2*m2],   ui0 = U_im[k * 16 + 2*m2];
        float ur1 = U_re[k * 16 + 2*m2+1], ui1 = U_im[k * 16 + 2*m2+1];
        M0 = fmaf(vk, fmaf(ur0, urn, ui0 * uin), M0);
        M1 = fmaf(vk, fmaf(ur1, urn, ui1 * uin), M1);
    }
    g_M[p * 128 + n * 8 + m2] = pack2(M0, M1);
}

// ---------------- kernel 1: per-patch quadratic forms ----------------
// block = (patch-row r, chunk of 256 images); thread = one image.
// All lanes share p each iteration -> smem M reads are uniform (broadcast).
#define K1_THREADS 256

__global__ __launch_bounds__(K1_THREADS)
void patch_kernel(const float* __restrict__ x, int bsz)
{
    __shared__ __align__(16) u64 sM[14 * 128];   // 14 KB: this row's 14 matrices

    const int r   = blockIdx.x;                  // 0..13 patch row
    const int tid = threadIdx.x;
    const int img = blockIdx.y * K1_THREADS + tid;
    const bool valid = img < bsz;

    for (int i = tid; i < 14 * 128; i += K1_THREADS)
        sM[i] = g_M[r * 14 * 128 + i];
    __syncthreads();

    const float* rowp = x + (size_t)(valid ? img : 0) * 784 + (2 * r) * 28;

    float s_q = 0.f, sp = 0.f, sqs = 0.f;

    #pragma unroll 2
    for (int c = 0; c < 14; c++) {
        float2 top = valid ? *reinterpret_cast<const float2*>(rowp + 2*c)
                           : make_float2(0.f, 0.f);
        float2 bot = valid ? *reinterpret_cast<const float2*>(rowp + 28 + 2*c)
                           : make_float2(0.f, 0.f);
        float x00 = top.x, x01 = top.y, x10 = bot.x, x11 = bot.y;

        sp  += x00 + x01 + x10 + x11;
        sqs += fmaf(x00,x00, fmaf(x01,x01, fmaf(x10,x10, x11*x11)));

        float c0,s0,c1,s1,c2,s2,c3,s3;
        __sincosf(0.5f*x00, &s0, &c0);
        __sincosf(0.5f*x01, &s1, &c1);
        __sincosf(0.5f*x10, &s2, &c2);
        __sincosf(0.5f*x11, &s3, &c3);
        float p01[4] = { c0*c1, c0*s1, s0*c1, s0*s1 };
        float p012[8];
        #pragma unroll
        for (int t2 = 0; t2 < 4; t2++){ p012[2*t2] = p01[t2]*c2; p012[2*t2+1] = p01[t2]*s2; }
        float psi[16];
        #pragma unroll
        for (int t2 = 0; t2 < 8; t2++){ psi[2*t2] = p012[t2]*c3; psi[2*t2+1] = p012[t2]*s3; }

        // y = M_p * psi  (packed row-pairs), then s_q += psi . y
        u64 acc[8];
        #pragma unroll
        for (int m2 = 0; m2 < 8; m2++) acc[m2] = 0ull;

        const ulonglong2* Mc = reinterpret_cast<const ulonglong2*>(sM + c * 128);
        #pragma unroll
        for (int n = 0; n < 16; n++) {
            u64 pn = pack2(psi[n], psi[n]);
            ulonglong2 q0 = Mc[n*4 + 0];   // uniform LDS.128 -> broadcast
            ulonglong2 q1 = Mc[n*4 + 1];
            ulonglong2 q2 = Mc[n*4 + 2];
            ulonglong2 q3 = Mc[n*4 + 3];
            acc[0] = fma2(q0.x, pn, acc[0]);
            acc[1] = fma2(q0.y, pn, acc[1]);
            acc[2] = fma2(q1.x, pn, acc[2]);
            acc[3] = fma2(q1.y, pn, acc[3]);
            acc[4] = fma2(q2.x, pn, acc[4]);
            acc[5] = fma2(q2.y, pn, acc[5]);
            acc[6] = fma2(q3.x, pn, acc[6]);
            acc[7] = fma2(q3.y, pn, acc[7]);
        }
        u64 d2 = 0ull;
        #pragma unroll
        for (int m2 = 0; m2 < 8; m2++)
            d2 = fma2(pack2(psi[2*m2], psi[2*m2+1]), acc[m2], d2);
        s_q += lo2(d2) + hi2(d2);
    }

    if (valid) {
        float* gp = g_part + ((size_t)img * 14 + r) * 3;
        gp[0] = s_q; gp[1] = sp; gp[2] = sqs;
    }
}

// ---------------- kernel 2: reduce + classical head + sigmoid ----------------
__global__ void head_kernel(
    const float* __restrict__ w_in,  const float* __restrict__ b_in,
    const float* __restrict__ scale_in, const float* __restrict__ shift_in,
    const float* __restrict__ Wc,    const float* __restrict__ bc,
    const float* __restrict__ scalec, const float* __restrict__ shiftc,
    const float* __restrict__ w_out, const float* __restrict__ b_out,
    const float* __restrict__ w_cls, const float* __restrict__ b_cls,
    float* __restrict__ out, int Lc, int bsz)
{
    int i = blockIdx.x * blockDim.x + threadIdx.x;
    if (i >= bsz) return;

    const float* gp = g_part + (size_t)i * 14 * 3;
    float Q = 0.f, S = 0.f, S2 = 0.f;
    #pragma unroll
    for (int r = 0; r < 14; r++) {
        Q  += gp[r*3 + 0];
        S  += gp[r*3 + 1];
        S2 += gp[r*3 + 2];
    }

    float mean = S * (1.f/784.f);
    float var  = (S2 - S*S*(1.f/784.f)) * (1.f/783.f);
    float stdv = sqrtf(fmaxf(var, 0.f));
    float h0 = mean, h1 = stdv;
    float t0 = tanhf(fmaf(w_in[0],h0, fmaf(w_in[1],h1, b_in[0]))) * scale_in[0] + shift_in[0];
    float t1 = tanhf(fmaf(w_in[2],h0, fmaf(w_in[3],h1, b_in[1]))) * scale_in[1] + shift_in[1];
    h0 = t0; h1 = t1;
    for (int l = 0; l < Lc; l++) {
        float u0 = tanhf(fmaf(Wc[l*4+0],h0, fmaf(Wc[l*4+1],h1, bc[l*2+0]))) * scalec[l*2+0] + shiftc[l*2+0];
        float u1 = tanhf(fmaf(Wc[l*4+2],h0, fmaf(Wc[l*4+3],h1, bc[l*2+1]))) * scalec[l*2+1] + shiftc[l*2+1];
        h0 = u0; h1 = u1;
    }
    float cls   = fmaf(w_out[0],h0, fmaf(w_out[1],h1, b_out[0]));
    float logit = fmaf(w_cls[0], cls, b_cls[0]) + Q;
    out[i] = 1.f / (1.f + expf(-logit));
}

// ---------------- launch ----------------
extern "C" void kernel_launch(void* const* d_in, const int* in_sizes, int n_in,
                              void* d_out, int out_size)
{
    const float* x        = (const float*)d_in[0];
    const float* w_in     = (const float*)d_in[1];
    const float* b_in     = (const float*)d_in[2];
    const float* scale_in = (const float*)d_in[3];
    const float* shift_in = (const float*)d_in[4];
    const float* Wc       = (const float*)d_in[5];
    const float* bc       = (const float*)d_in[6];
    const float* scalec   = (const float*)d_in[7];
    const float* shiftc   = (const float*)d_in[8];
    const float* w_out    = (const float*)d_in[9];
    const float* b_out    = (const float*)d_in[10];
    const float* U_re     = (const float*)d_in[11];
    const float* U_im     = (const float*)d_in[12];
    const float* w_cls    = (const float*)d_in[13];
    const float* b_cls    = (const float*)d_in[14];
    float* out = (float*)d_out;

    const int bsz = in_sizes[0] / 784;
    const int Lc  = in_sizes[5] / 4;

    build_M_kernel<<<196, 128>>>(U_re, U_im, w_cls);

    dim3 grid1(14, (bsz + K1_THREADS - 1) / K1_THREADS);
    patch_kernel<<<grid1, K1_THREADS>>>(x, bsz);

    head_kernel<<<(bsz + 255) / 256, 256>>>(w_in, b_in, scale_in, shift_in,
                                            Wc, bc, scalec, shiftc,
                                            w_out, b_out, w_cls, b_cls,
                                            out, Lc, bsz);
}

// round 6
// speedup vs baseline: 1.7651x; 1.1634x over previous
#include <cuda_runtime.h>
#include <cstdint>
#include <math.h>

typedef uint32_t u32;
typedef unsigned long long u64;

__device__ __forceinline__ u64 pack2(float lo, float hi){
    u64 d; asm("mov.b64 %0, {%1, %2};" : "=l"(d) : "f"(lo), "f"(hi)); return d;
}
__device__ __forceinline__ u64 fma2(u64 a, u64 b, u64 c){
    u64 d; asm("fma.rn.f32x2 %0, %1, %2, %3;" : "=l"(d) : "l"(a), "l"(b), "l"(c)); return d;
}
__device__ __forceinline__ u64 add2(u64 a, u64 b){
    u64 d; asm("add.rn.f32x2 %0, %1, %2;" : "=l"(d) : "l"(a), "l"(b)); return d;
}
__device__ __forceinline__ float lo2(u64 v){ return __int_as_float((unsigned)(v & 0xffffffffull)); }
__device__ __forceinline__ float hi2(u64 v){ return __int_as_float((unsigned)(v >> 32)); }

// ---------------- scratch ----------------
// G[L][k]: fixed 81x16 transform from v_k weights to trig-poly coefficients.
// L = t3*27 + t0*9 + t1*3 + t2  (t_q in {0:const, 1:cos, 2:sin}, qubit q = patch pixel q)
__device__ float g_G[81 * 16];
// C[p][L]: per-patch trig-poly coefficients (p = r*14 + c)
__device__ float g_C[196 * 81];
// per-(image, patch-row) partials: [img][r][{s_q, sum, sumsq}]
__device__ float g_part[16384 * 14 * 3];

// ---------------- kernel 0: build G (once, tiny) ----------------
// G[L][k] = (1/16) * sum over 2^4 per-qubit choices of sign * (ur[k][m]ur[k][n] + ui[k][m]ui[k][n])
// per qubit q with digit t_q:  t=0: (o,o,+)  t=1: (o,o, o? - : +)  t=2: (o,1-o,+)
// bit position of qubit q in m,n is (3-q).
__global__ void build_G_kernel(const float* __restrict__ U_re,
                               const float* __restrict__ U_im)
{
    __shared__ float sur[256], sui[256];
    const int tid = threadIdx.x;
    if (tid < 256) { sur[tid] = U_re[tid]; sui[tid] = U_im[tid]; }
    __syncthreads();

    for (int e = tid; e < 81 * 16; e += blockDim.x) {
        int L = e >> 4, k = e & 15;
        int t3 = L / 27, r27 = L - 27 * t3;
        int t0 = r27 / 9, r9 = r27 - 9 * t0;
        int t1 = r9 / 3,  t2 = r9 - 3 * t1;
        int tq[4] = { t0, t1, t2, t3 };

        float acc = 0.f;
        #pragma unroll 1
        for (int ch = 0; ch < 16; ch++) {
            int m = 0, n = 0; float sg = 1.f;
            #pragma unroll
            for (int q = 0; q < 4; q++) {
                int o = (ch >> q) & 1;
                int tv = tq[q];
                int bm, bn;
                if (tv == 2) { bm = o; bn = 1 - o; }
                else         { bm = o; bn = o; if (tv == 1 && o) sg = -sg; }
                m |= bm << (3 - q);
                n |= bn << (3 - q);
            }
            acc += sg * (sur[k * 16 + m] * sur[k * 16 + n] +
                         sui[k * 16 + m] * sui[k * 16 + n]);
        }
        g_G[e] = acc * (1.f / 16.f);
    }
}

// ---------------- kernel 1: build C (196 x 81, light) ----------------
// v_k(p) = sum_j w_cls[1+4p+j] * Z[k][j], Z[k][j] = 1-2*((k>>(3-j))&1)
__global__ void build_C_kernel(const float* __restrict__ w_cls)
{
    const int p = blockIdx.x;
    const int L = threadIdx.x;
    if (L >= 81) return;
    const float* wq = w_cls + 1 + 4 * p;
    const float w0 = wq[0], w1 = wq[1], w2 = wq[2], w3 = wq[3];
    float acc = 0.f;
    #pragma unroll
    for (int k = 0; k < 16; k++) {
        float vk = ((k & 8) ? -w0 : w0) + ((k & 4) ? -w1 : w1)
                 + ((k & 2) ? -w2 : w2) + ((k & 1) ? -w3 : w3);
        acc = fmaf(vk, g_G[L * 16 + k], acc);
    }
    g_C[p * 81 + L] = acc;
}

// ---------------- kernel 2: per-patch trig-poly eval ----------------
// block = (patch row r, chunk of 256 images); thread = one image.
// Two patch columns packed per f32x2 lane-pair -> 7 packed pairs per row.
// smem layout per pair j: 3 planes (t3 = 0,1,2) of 27 packed u64, pitch 28.
#define K1_THREADS 256

__global__ __launch_bounds__(K1_THREADS)
void patch_kernel(const float* __restrict__ x, int bsz)
{
    __shared__ __align__(16) u64 sC[7 * 84];   // 4704 B

    const int r   = blockIdx.x;                // 0..13
    const int tid = threadIdx.x;
    const int img = blockIdx.y * K1_THREADS + tid;
    const bool valid = img < bsz;

    // fill: pack columns (2j, 2j+1) into f32x2 halves, plane-major by t3
    for (int i = tid; i < 7 * 81; i += K1_THREADS) {
        int j = i / 81, L = i - 81 * j;
        int t3 = L / 27, i012 = L - 27 * t3;
        const float* cp = g_C + (r * 14 + 2 * j) * 81 + L;
        sC[j * 84 + t3 * 28 + i012] = pack2(cp[0], cp[81]);
    }
    __syncthreads();

    const float* rowp = x + (size_t)(valid ? img : 0) * 784 + (2 * r) * 28;

    u64 sQ = 0ull;
    float sp = 0.f, sqs = 0.f;

    #pragma unroll 1
    for (int j = 0; j < 7; j++) {
        float4 r0 = *reinterpret_cast<const float4*>(rowp + 4 * j);
        float4 r1 = *reinterpret_cast<const float4*>(rowp + 28 + 4 * j);

        sp  += (r0.x + r0.y + r0.z + r0.w) + (r1.x + r1.y + r1.z + r1.w);
        sqs += fmaf(r0.x,r0.x, fmaf(r0.y,r0.y, fmaf(r0.z,r0.z, r0.w*r0.w)))
             + fmaf(r1.x,r1.x, fmaf(r1.y,r1.y, fmaf(r1.z,r1.z, r1.w*r1.w)));

        // patch a (col 2j): pixels r0.x r0.y r1.x r1.y ; patch b (col 2j+1): r0.z r0.w r1.z r1.w
        float ca0,sa0,ca1,sa1,ca2,sa2,ca3,sa3;
        float cb0,sb0,cb1,sb1,cb2,sb2,cb3,sb3;
        __sincosf(r0.x, &sa0, &ca0);  __sincosf(r0.y, &sa1, &ca1);
        __sincosf(r1.x, &sa2, &ca2);  __sincosf(r1.y, &sa3, &ca3);
        __sincosf(r0.z, &sb0, &cb0);  __sincosf(r0.w, &sb1, &cb1);
        __sincosf(r1.z, &sb2, &cb2);  __sincosf(r1.w, &sb3, &cb3);

        u64 Fc0 = pack2(ca0, cb0), Fs0 = pack2(sa0, sb0);
        u64 Fc1 = pack2(ca1, cb1), Fs1 = pack2(sa1, sb1);
        u64 Fc2 = pack2(ca2, cb2), Fs2 = pack2(sa2, sb2);
        u64 Fc3 = pack2(ca3, cb3), Fs3 = pack2(sa3, sb3);

        const u64* Cj = sC + j * 84;

        // contract qubit 3 (t3 planes): g2[i012] = C0[i] + C1[i]*cos + C2[i]*sin
        u64 g2[27];
        #pragma unroll
        for (int i = 0; i < 26; i += 2) {
            ulonglong2 a = *reinterpret_cast<const ulonglong2*>(Cj + i);
            ulonglong2 b = *reinterpret_cast<const ulonglong2*>(Cj + 28 + i);
            ulonglong2 c = *reinterpret_cast<const ulonglong2*>(Cj + 56 + i);
            g2[i]   = fma2(c.x, Fs3, fma2(b.x, Fc3, a.x));
            g2[i+1] = fma2(c.y, Fs3, fma2(b.y, Fc3, a.y));
        }
        g2[26] = fma2(Cj[56+26], Fs3, fma2(Cj[28+26], Fc3, Cj[26]));

        // contract qubit 2 (t2 fastest within i012)
        u64 g1[9];
        #pragma unroll
        for (int i01 = 0; i01 < 9; i01++)
            g1[i01] = fma2(g2[3*i01+2], Fs2, fma2(g2[3*i01+1], Fc2, g2[3*i01]));

        // contract qubit 1, then qubit 0
        u64 h0 = fma2(g1[2], Fs1, fma2(g1[1], Fc1, g1[0]));
        u64 h1 = fma2(g1[5], Fs1, fma2(g1[4], Fc1, g1[3]));
        u64 h2 = fma2(g1[8], Fs1, fma2(g1[7], Fc1, g1[6]));
        u64 s  = fma2(h2, Fs0, fma2(h1, Fc0, h0));

        sQ = add2(sQ, s);
    }

    if (valid) {
        float* gp = g_part + ((size_t)img * 14 + r) * 3;
        gp[0] = lo2(sQ) + hi2(sQ);
        gp[1] = sp;
        gp[2] = sqs;
    }
}

// ---------------- kernel 3: reduce + classical head + sigmoid ----------------
__global__ void head_kernel(
    const float* __restrict__ w_in,  const float* __restrict__ b_in,
    const float* __restrict__ scale_in, const float* __restrict__ shift_in,
    const float* __restrict__ Wc,    const float* __restrict__ bc,
    const float* __restrict__ scalec, const float* __restrict__ shiftc,
    const float* __restrict__ w_out, const float* __restrict__ b_out,
    const float* __restrict__ w_cls, const float* __restrict__ b_cls,
    float* __restrict__ out, int Lc, int bsz)
{
    int i = blockIdx.x * blockDim.x + threadIdx.x;
    if (i >= bsz) return;

    const float* gp = g_part + (size_t)i * 14 * 3;
    float Q = 0.f, S = 0.f, S2 = 0.f;
    #pragma unroll
    for (int r = 0; r < 14; r++) {
        Q  += gp[r*3 + 0];
        S  += gp[r*3 + 1];
        S2 += gp[r*3 + 2];
    }

    float mean = S * (1.f/784.f);
    float var  = (S2 - S*S*(1.f/784.f)) * (1.f/783.f);
    float stdv = sqrtf(fmaxf(var, 0.f));
    float h0 = mean, h1 = stdv;
    float t0 = tanhf(fmaf(w_in[0],h0, fmaf(w_in[1],h1, b_in[0]))) * scale_in[0] + shift_in[0];
    float t1 = tanhf(fmaf(w_in[2],h0, fmaf(w_in[3],h1, b_in[1]))) * scale_in[1] + shift_in[1];
    h0 = t0; h1 = t1;
    for (int l = 0; l < Lc; l++) {
        float u0 = tanhf(fmaf(Wc[l*4+0],h0, fmaf(Wc[l*4+1],h1, bc[l*2+0]))) * scalec[l*2+0] + shiftc[l*2+0];
        float u1 = tanhf(fmaf(Wc[l*4+2],h0, fmaf(Wc[l*4+3],h1, bc[l*2+1]))) * scalec[l*2+1] + shiftc[l*2+1];
        h0 = u0; h1 = u1;
    }
    float cls   = fmaf(w_out[0],h0, fmaf(w_out[1],h1, b_out[0]));
    float logit = fmaf(w_cls[0], cls, b_cls[0]) + Q;
    out[i] = 1.f / (1.f + expf(-logit));
}

// ---------------- launch ----------------
extern "C" void kernel_launch(void* const* d_in, const int* in_sizes, int n_in,
                              void* d_out, int out_size)
{
    const float* x        = (const float*)d_in[0];
    const float* w_in     = (const float*)d_in[1];
    const float* b_in     = (const float*)d_in[2];
    const float* scale_in = (const float*)d_in[3];
    const float* shift_in = (const float*)d_in[4];
    const float* Wc       = (const float*)d_in[5];
    const float* bc       = (const float*)d_in[6];
    const float* scalec   = (const float*)d_in[7];
    const float* shiftc   = (const float*)d_in[8];
    const float* w_out    = (const float*)d_in[9];
    const float* b_out    = (const float*)d_in[10];
    const float* U_re     = (const float*)d_in[11];
    const float* U_im     = (const float*)d_in[12];
    const float* w_cls    = (const float*)d_in[13];
    const float* b_cls    = (const float*)d_in[14];
    float* out = (float*)d_out;

    const int bsz = in_sizes[0] / 784;
    const int Lc  = in_sizes[5] / 4;

    build_G_kernel<<<1, 512>>>(U_re, U_im);
    build_C_kernel<<<196, 96>>>(w_cls);

    dim3 grid1(14, (bsz + K1_THREADS - 1) / K1_THREADS);
    patch_kernel<<<grid1, K1_THREADS>>>(x, bsz);

    head_kernel<<<(bsz + 255) / 256, 256>>>(w_in, b_in, scale_in, shift_in,
                                            Wc, bc, scalec, shiftc,
                                            w_out, b_out, w_cls, b_cls,
                                            out, Lc, bsz);
}

// round 7
// speedup vs baseline: 2.2741x; 1.2884x over previous
#include <cuda_runtime.h>
#include <cstdint>
#include <math.h>

typedef uint32_t u32;
typedef unsigned long long u64;

__device__ __forceinline__ u64 pack2(float lo, float hi){
    u64 d; asm("mov.b64 %0, {%1, %2};" : "=l"(d) : "f"(lo), "f"(hi)); return d;
}
__device__ __forceinline__ u64 fma2(u64 a, u64 b, u64 c){
    u64 d; asm("fma.rn.f32x2 %0, %1, %2, %3;" : "=l"(d) : "l"(a), "l"(b), "l"(c)); return d;
}
__device__ __forceinline__ u64 add2(u64 a, u64 b){
    u64 d; asm("add.rn.f32x2 %0, %1, %2;" : "=l"(d) : "l"(a), "l"(b)); return d;
}
__device__ __forceinline__ float lo2(u64 v){ return __int_as_float((unsigned)(v & 0xffffffffull)); }
__device__ __forceinline__ float hi2(u64 v){ return __int_as_float((unsigned)(v >> 32)); }
__device__ __forceinline__ float tanha(float v){
    float r; asm("tanh.approx.f32 %0, %1;" : "=f"(r) : "f"(v)); return r;
}

// ---------------- scratch ----------------
// G[L][k]: fixed 81x16 transform. L = t3*27 + t0*9 + t1*3 + t2.
__device__ float g_G[81 * 16];
// packed per-(row,pair) coefficients, patch-ready layout:
// g_Cpk[(r*7+j)*90 + i01*10 + t3*3 + t2] = pack2(C[p=2j], C[p=2j+1]); i01 = t0*3+t1
__device__ u64 g_Cpk[98 * 90];
// transposed partials: g_part[(r*3+q)*16384 + img], q in {Q, S, S2}
__device__ float g_part[42 * 16384];

// ---------------- kernel 0: build G (6 blocks x 216 = 1296 entries) ----------------
__global__ void build_G_kernel(const float* __restrict__ U_re,
                               const float* __restrict__ U_im)
{
    __shared__ float sur[256], sui[256];
    const int tid = threadIdx.x;
    for (int i = tid; i < 256; i += blockDim.x) { sur[i] = U_re[i]; sui[i] = U_im[i]; }
    __syncthreads();

    int e = blockIdx.x * blockDim.x + tid;
    if (e >= 81 * 16) return;
    int L = e >> 4, k = e & 15;
    int t3 = L / 27, r27 = L - 27 * t3;
    int t0 = r27 / 9, r9 = r27 - 9 * t0;
    int t1 = r9 / 3,  t2 = r9 - 3 * t1;
    int tq[4] = { t0, t1, t2, t3 };

    float acc = 0.f;
    #pragma unroll 1
    for (int ch = 0; ch < 16; ch++) {
        int m = 0, n = 0; float sg = 1.f;
        #pragma unroll
        for (int q = 0; q < 4; q++) {
            int o = (ch >> q) & 1;
            int tv = tq[q];
            int bm, bn;
            if (tv == 2) { bm = o; bn = 1 - o; }
            else         { bm = o; bn = o; if (tv == 1 && o) sg = -sg; }
            m |= bm << (3 - q);
            n |= bn << (3 - q);
        }
        acc += sg * (sur[k * 16 + m] * sur[k * 16 + n] +
                     sui[k * 16 + m] * sui[k * 16 + n]);
    }
    g_G[e] = acc * (1.f / 16.f);
}

// ---------------- kernel 1: build packed C (98 blocks x 96) ----------------
__global__ void build_C_kernel(const float* __restrict__ w_cls)
{
    const int blk = blockIdx.x;          // r*7 + j
    const int L = threadIdx.x;
    if (L >= 81) return;
    const int p0 = 2 * blk;              // r*14 + 2j
    const float* wa = w_cls + 1 + 4 * p0;
    const float* wb = wa + 4;
    float a0 = wa[0], a1 = wa[1], a2 = wa[2], a3 = wa[3];
    float b0 = wb[0], b1 = wb[1], b2 = wb[2], b3 = wb[3];

    float accA = 0.f, accB = 0.f;
    #pragma unroll
    for (int k = 0; k < 16; k++) {
        float g = g_G[L * 16 + k];
        float vA = ((k & 8) ? -a0 : a0) + ((k & 4) ? -a1 : a1)
                 + ((k & 2) ? -a2 : a2) + ((k & 1) ? -a3 : a3);
        float vB = ((k & 8) ? -b0 : b0) + ((k & 4) ? -b1 : b1)
                 + ((k & 2) ? -b2 : b2) + ((k & 1) ? -b3 : b3);
        accA = fmaf(vA, g, accA);
        accB = fmaf(vB, g, accB);
    }
    int t3 = L / 27, rem = L - 27 * t3;
    int t0 = rem / 9, r9 = rem - 9 * t0;
    int t1 = r9 / 3,  t2 = r9 - 3 * t1;
    int i01 = t0 * 3 + t1;
    g_Cpk[blk * 90 + i01 * 10 + t3 * 3 + t2] = pack2(accA, accB);
}

// ---------------- kernel 2: per-patch trig-poly eval ----------------
#define PK_THREADS 128

__global__ __launch_bounds__(PK_THREADS)
void patch_kernel(const float* __restrict__ x, int bsz)
{
    __shared__ __align__(16) u64 sC[7 * 90];        // 5040 B
    __shared__ float spx[PK_THREADS * 58];          // 29696 B, pitch 58 (odd/2 -> few conflicts)

    const int r    = blockIdx.x;                    // 0..13
    const int tid  = threadIdx.x;
    const int img0 = blockIdx.y * PK_THREADS;
    const int img  = img0 + tid;
    const int nimg = min(PK_THREADS, bsz - img0);

    for (int i = tid; i < 7 * 90; i += PK_THREADS)
        sC[i] = g_Cpk[r * 630 + i];

    // coalesced pixel staging: rows 2r,2r+1 = 56 contiguous floats per image
    const float* xbase = x + (size_t)img0 * 784 + r * 56;
    for (int idx = tid; idx < PK_THREADS * 56; idx += PK_THREADS) {
        int i = idx / 56, f = idx - i * 56;
        spx[i * 58 + f] = (i < nimg) ? xbase[(size_t)i * 784 + f] : 0.f;
    }
    __syncthreads();

    const float* my = spx + tid * 58;    // [0..27]=row 2r, [28..55]=row 2r+1
    const u64 ONEv = pack2(1.f, 1.f);

    u64 sQ = 0ull;
    float sp = 0.f, sqs = 0.f;

    #pragma unroll 1
    for (int j = 0; j < 7; j++) {
        float2 a01 = *reinterpret_cast<const float2*>(my + 4 * j);        // x00a, x01a
        float2 b01 = *reinterpret_cast<const float2*>(my + 4 * j + 2);    // x00b, x01b
        float2 a23 = *reinterpret_cast<const float2*>(my + 28 + 4 * j);   // x10a, x11a
        float2 b23 = *reinterpret_cast<const float2*>(my + 30 + 4 * j);   // x10b, x11b

        sp  += (a01.x + a01.y + b01.x + b01.y) + (a23.x + a23.y + b23.x + b23.y);
        sqs += fmaf(a01.x,a01.x, fmaf(a01.y,a01.y, fmaf(b01.x,b01.x, b01.y*b01.y)))
             + fmaf(a23.x,a23.x, fmaf(a23.y,a23.y, fmaf(b23.x,b23.x, b23.y*b23.y)));

        float ca0,sa0,ca1,sa1,ca2,sa2,ca3,sa3;
        float cb0,sb0,cb1,sb1,cb2,sb2,cb3,sb3;
        __sincosf(a01.x, &sa0, &ca0);  __sincosf(a01.y, &sa1, &ca1);
        __sincosf(a23.x, &sa2, &ca2);  __sincosf(a23.y, &sa3, &ca3);
        __sincosf(b01.x, &sb0, &cb0);  __sincosf(b01.y, &sb1, &cb1);
        __sincosf(b23.x, &sb2, &cb2);  __sincosf(b23.y, &sb3, &cb3);

        u64 Fc0 = pack2(ca0, cb0), Fs0 = pack2(sa0, sb0);
        u64 Fc1 = pack2(ca1, cb1), Fs1 = pack2(sa1, sb1);
        u64 Fc2 = pack2(ca2, cb2), Fs2 = pack2(sa2, sb2);
        u64 Fc3 = pack2(ca3, cb3), Fs3 = pack2(sa3, sb3);

        const u64* Cj = sC + j * 90;
        u64 h0 = 0ull, h1 = 0ull, h2 = 0ull;

        #pragma unroll
        for (int i01 = 0; i01 < 9; i01++) {
            const u64* base = Cj + i01 * 10;   // 16B aligned (10 u64 pitch)
            ulonglong2 q01 = *reinterpret_cast<const ulonglong2*>(base + 0);
            ulonglong2 q23 = *reinterpret_cast<const ulonglong2*>(base + 2);
            ulonglong2 q45 = *reinterpret_cast<const ulonglong2*>(base + 4);
            ulonglong2 q67 = *reinterpret_cast<const ulonglong2*>(base + 6);
            u64 q8 = base[8];
            // a_t2 = q[t2] + q[3+t2]*Fc3 + q[6+t2]*Fs3
            u64 av0 = fma2(q67.x, Fs3, fma2(q23.y, Fc3, q01.x));
            u64 av1 = fma2(q67.y, Fs3, fma2(q45.x, Fc3, q01.y));
            u64 av2 = fma2(q8,    Fs3, fma2(q45.y, Fc3, q23.x));
            u64 g   = fma2(av2, Fs2, fma2(av1, Fc2, av0));
            const int t1v = i01 % 3;
            u64 w = (t1v == 0) ? ONEv : ((t1v == 1) ? Fc1 : Fs1);
            if (i01 < 3)      h0 = fma2(g, w, h0);
            else if (i01 < 6) h1 = fma2(g, w, h1);
            else              h2 = fma2(g, w, h2);
        }
        sQ = add2(sQ, fma2(h2, Fs0, fma2(h1, Fc0, h0)));
    }

    if (img < bsz) {
        g_part[(r * 3 + 0) * 16384 + img] = lo2(sQ) + hi2(sQ);
        g_part[(r * 3 + 1) * 16384 + img] = sp;
        g_part[(r * 3 + 2) * 16384 + img] = sqs;
    }
}

// ---------------- kernel 3: reduce + classical head + sigmoid ----------------
__global__ void head_kernel(
    const float* __restrict__ w_in,  const float* __restrict__ b_in,
    const float* __restrict__ scale_in, const float* __restrict__ shift_in,
    const float* __restrict__ Wc,    const float* __restrict__ bc,
    const float* __restrict__ scalec, const float* __restrict__ shiftc,
    const float* __restrict__ w_out, const float* __restrict__ b_out,
    const float* __restrict__ w_cls, const float* __restrict__ b_cls,
    float* __restrict__ out, int Lc, int bsz)
{
    int i = blockIdx.x * blockDim.x + threadIdx.x;
    if (i >= bsz) return;

    float Q = 0.f, S = 0.f, S2 = 0.f;
    #pragma unroll
    for (int r = 0; r < 14; r++) {
        Q  += g_part[(r * 3 + 0) * 16384 + i];
        S  += g_part[(r * 3 + 1) * 16384 + i];
        S2 += g_part[(r * 3 + 2) * 16384 + i];
    }

    float mean = S * (1.f/784.f);
    float var  = (S2 - S*S*(1.f/784.f)) * (1.f/783.f);
    float stdv = sqrtf(fmaxf(var, 0.f));
    float h0 = mean, h1 = stdv;
    float t0 = tanha(fmaf(w_in[0],h0, fmaf(w_in[1],h1, b_in[0]))) * scale_in[0] + shift_in[0];
    float t1 = tanha(fmaf(w_in[2],h0, fmaf(w_in[3],h1, b_in[1]))) * scale_in[1] + shift_in[1];
    h0 = t0; h1 = t1;
    for (int l = 0; l < Lc; l++) {
        float u0 = tanha(fmaf(Wc[l*4+0],h0, fmaf(Wc[l*4+1],h1, bc[l*2+0]))) * scalec[l*2+0] + shiftc[l*2+0];
        float u1 = tanha(fmaf(Wc[l*4+2],h0, fmaf(Wc[l*4+3],h1, bc[l*2+1]))) * scalec[l*2+1] + shiftc[l*2+1];
        h0 = u0; h1 = u1;
    }
    float cls   = fmaf(w_out[0],h0, fmaf(w_out[1],h1, b_out[0]));
    float logit = fmaf(w_cls[0], cls, b_cls[0]) + Q;
    out[i] = 1.f / (1.f + __expf(-logit));
}

// ---------------- launch ----------------
extern "C" void kernel_launch(void* const* d_in, const int* in_sizes, int n_in,
                              void* d_out, int out_size)
{
    const float* x        = (const float*)d_in[0];
    const float* w_in     = (const float*)d_in[1];
    const float* b_in     = (const float*)d_in[2];
    const float* scale_in = (const float*)d_in[3];
    const float* shift_in = (const float*)d_in[4];
    const float* Wc       = (const float*)d_in[5];
    const float* bc       = (const float*)d_in[6];
    const float* scalec   = (const float*)d_in[7];
    const float* shiftc   = (const float*)d_in[8];
    const float* w_out    = (const float*)d_in[9];
    const float* b_out    = (const float*)d_in[10];
    const float* U_re     = (const float*)d_in[11];
    const float* U_im     = (const float*)d_in[12];
    const float* w_cls    = (const float*)d_in[13];
    const float* b_cls    = (const float*)d_in[14];
    float* out = (float*)d_out;

    const int bsz = in_sizes[0] / 784;
    const int Lc  = in_sizes[5] / 4;

    build_G_kernel<<<6, 216>>>(U_re, U_im);
    build_C_kernel<<<98, 96>>>(w_cls);

    dim3 grid1(14, (bsz + PK_THREADS - 1) / PK_THREADS);
    patch_kernel<<<grid1, PK_THREADS>>>(x, bsz);

    head_kernel<<<(bsz + 127) / 128, 128>>>(w_in, b_in, scale_in, shift_in,
                                            Wc, bc, scalec, shiftc,
                                            w_out, b_out, w_cls, b_cls,
                                            out, Lc, bsz);
}